// round 4
// baseline (speedup 1.0000x reference)
#include <cuda_runtime.h>
#include <cuda_bf16.h>
#include <math.h>

// Problem constants (fixed by the reference)
#define F_IN   512
#define F_HID  256
#define F_OUT  40
#define MAXN   100000
#define MAXE   3200000

// ---------------- scratch (device globals; no runtime allocation) ----------------
__device__ int   g_is32;               // 1 if edge_index is int32, 0 if int64
__device__ int   g_eidx[2 * MAXE];     // converted edge list: [row(E), col(E)]
__device__ int   g_deg[MAXN];          // col-degree (init 1 for self-loop)
__device__ int   g_cnt[MAXN];          // row counts (for CSR)
__device__ float g_dinv[MAXN];
__device__ int   g_rowptr[MAXN + 1];
__device__ int   g_cursor[MAXN];
__device__ int   g_adj[MAXE];
__device__ int   g_part[256];
__device__ float g_w2t[F_OUT * F_HID]; // W2 transposed [o][f]
__device__ float g_h [(long)MAXN * F_HID];  // h_s = dinv[i] * (x @ W1)
__device__ float g_h2[(long)MAXN * F_OUT];  // h2_s = dinv[i] * (relu(...) @ W2)

// ---------------- dtype detect + convert ----------------
__global__ void k_init(int n) {
    int i = blockIdx.x * blockDim.x + threadIdx.x;
    if (i < n) { g_deg[i] = 1; g_cnt[i] = 0; }
    if (i == 0) g_is32 = 0;
}

// Read buffer as int64; any value outside [0, n) => data is really int32.
__global__ void k_detect(const long long* __restrict__ ei, int E, int n) {
    int bad = 0;
    for (long e = blockIdx.x * blockDim.x + threadIdx.x; e < (long)E; e += (long)gridDim.x * blockDim.x) {
        long long v = ei[e];
        if (v < 0 || v >= n) bad = 1;
    }
    if (__syncthreads_or(bad)) {
        if (threadIdx.x == 0) g_is32 = 1;
    }
}

__global__ void k_convert(const void* __restrict__ ei_raw, int E, int n) {
    int is32 = g_is32;
    const int*       e32 = (const int*)ei_raw;
    const long long* e64 = (const long long*)ei_raw;
    for (long e = blockIdx.x * blockDim.x + threadIdx.x; e < 2L * E; e += (long)gridDim.x * blockDim.x) {
        long long v = is32 ? (long long)e32[e] : e64[e];
        if (v < 0) v = 0;
        if (v >= n) v = n - 1;   // clamp: address-space safety (identity on valid data)
        g_eidx[e] = (int)v;
    }
}

// ---------------- degree / histogram ----------------
__global__ void k_hist(int E) {
    for (int e = blockIdx.x * blockDim.x + threadIdx.x; e < E; e += gridDim.x * blockDim.x) {
        int r = g_eidx[e];
        int c = g_eidx[E + e];
        atomicAdd(&g_deg[c], 1);
        atomicAdd(&g_cnt[r], 1);
    }
}

__global__ void k_dinv(int n) {
    int i = blockIdx.x * blockDim.x + threadIdx.x;
    if (i < n) g_dinv[i] = rsqrtf((float)g_deg[i]);
}

// ---------------- CSR build: scan over g_cnt ----------------
__global__ void k_scan1(int n) {
    __shared__ int s[1024];
    int tid = threadIdx.x;
    int idx = blockIdx.x * 1024 + tid;
    int v = (idx < n) ? g_cnt[idx] : 0;
    s[tid] = v;
    __syncthreads();
    for (int off = 1; off < 1024; off <<= 1) {
        int t = (tid >= off) ? s[tid - off] : 0;
        __syncthreads();
        s[tid] += t;
        __syncthreads();
    }
    if (idx < n) g_rowptr[idx] = s[tid] - v;   // local exclusive
    if (tid == 1023) g_part[blockIdx.x] = s[1023];
}

__global__ void k_scan2(int nb) {
    __shared__ int s[256];
    int tid = threadIdx.x;
    int v = (tid < nb) ? g_part[tid] : 0;
    s[tid] = v;
    __syncthreads();
    for (int off = 1; off < 256; off <<= 1) {
        int t = (tid >= off) ? s[tid - off] : 0;
        __syncthreads();
        s[tid] += t;
        __syncthreads();
    }
    if (tid < nb) g_part[tid] = s[tid] - v;    // exclusive
}

__global__ void k_scan3(int n, int E) {
    int i = blockIdx.x * blockDim.x + threadIdx.x;
    if (i < n) {
        int rp = g_rowptr[i] + g_part[i >> 10];
        g_rowptr[i] = rp;
        g_cursor[i] = rp;
    }
    if (blockIdx.x == 0 && threadIdx.x == 0) g_rowptr[n] = E;
}

__global__ void k_fill(int E) {
    for (int e = blockIdx.x * blockDim.x + threadIdx.x; e < E; e += gridDim.x * blockDim.x) {
        int r = g_eidx[e];
        int c = g_eidx[E + e];
        int pos = atomicAdd(&g_cursor[r], 1);
        g_adj[pos] = c;
    }
}

// ---------------- transpose W2 into [o][f] ----------------
__global__ void k_tw2(const float* __restrict__ W2) {
    int idx = blockIdx.x * blockDim.x + threadIdx.x;
    if (idx < F_OUT * F_HID) {
        int o = idx / F_HID, f = idx % F_HID;
        g_w2t[idx] = W2[f * F_OUT + o];
    }
}

// ---------------- SGEMM1: g_h[i][c] = dinv[i] * sum_k x[i][k] * W1[k][c] ----------------
// M x 512 @ 512 x 256, fp32. 128x128 tile, BK=8, 256 threads, 8x8 per thread.
__global__ __launch_bounds__(256) void k_sgemm1(const float* __restrict__ A,
                                                const float* __restrict__ B, int M) {
    const int K = F_IN, NN = F_HID;
    __shared__ float As[8][128];
    __shared__ float Bs[8][128];
    int bx = blockIdx.x;            // 0..1 (column block)
    int by = blockIdx.y;
    int tid = threadIdx.x;
    int trow = tid >> 4, tcol = tid & 15;
    int aRow = tid >> 1, aCol = (tid & 1) << 2;
    int bRow = tid >> 5, bCol = (tid & 31) << 2;
    long mBase = (long)by * 128;
    const float* Bg = B + bx * 128;

    float acc[8][8];
#pragma unroll
    for (int i = 0; i < 8; i++)
#pragma unroll
        for (int j = 0; j < 8; j++) acc[i][j] = 0.f;

    for (int k0 = 0; k0 < K; k0 += 8) {
        long gr = mBase + aRow;
        float4 a4 = make_float4(0.f, 0.f, 0.f, 0.f);
        if (gr < M) a4 = *(const float4*)(A + gr * K + k0 + aCol);
        As[aCol + 0][aRow] = a4.x;
        As[aCol + 1][aRow] = a4.y;
        As[aCol + 2][aRow] = a4.z;
        As[aCol + 3][aRow] = a4.w;
        float4 b4 = *(const float4*)(Bg + (long)(k0 + bRow) * NN + bCol);
        *(float4*)&Bs[bRow][bCol] = b4;
        __syncthreads();
#pragma unroll
        for (int kk = 0; kk < 8; kk++) {
            float ar[8], br[8];
            *(float4*)&ar[0] = *(float4*)&As[kk][trow * 8];
            *(float4*)&ar[4] = *(float4*)&As[kk][trow * 8 + 4];
            *(float4*)&br[0] = *(float4*)&Bs[kk][tcol * 8];
            *(float4*)&br[4] = *(float4*)&Bs[kk][tcol * 8 + 4];
#pragma unroll
            for (int i = 0; i < 8; i++)
#pragma unroll
                for (int j = 0; j < 8; j++) acc[i][j] = fmaf(ar[i], br[j], acc[i][j]);
        }
        __syncthreads();
    }
#pragma unroll
    for (int i = 0; i < 8; i++) {
        long r = mBase + trow * 8 + i;
        if (r < M) {
            float dv = g_dinv[r];
            float* cp = g_h + r * NN + bx * 128 + tcol * 8;
            float4 o0 = make_float4(acc[i][0] * dv, acc[i][1] * dv, acc[i][2] * dv, acc[i][3] * dv);
            float4 o1 = make_float4(acc[i][4] * dv, acc[i][5] * dv, acc[i][6] * dv, acc[i][7] * dv);
            *(float4*)cp       = o0;
            *(float4*)(cp + 4) = o1;
        }
    }
}

// ---------------- agg1 + bias + relu + GEMM2 fused ----------------
// block of 256 threads per node (grid-stride). h fits in L2 -> gathers hit L2.
__global__ __launch_bounds__(256) void k_agg1(const float* __restrict__ b1, int n) {
    __shared__ float w2s[F_OUT * F_HID];   // 40 KB, loaded once per block
    __shared__ float hsm[F_HID];
    __shared__ int   jsm[256];
    int tid = threadIdx.x;
    for (int idx = tid; idx < F_OUT * F_HID; idx += 256) w2s[idx] = g_w2t[idx];
    __syncthreads();

    int lane = tid & 31, w = tid >> 5;
    float bias = b1[tid];

    for (int i = blockIdx.x; i < n; i += gridDim.x) {
        int start = g_rowptr[i];
        int end   = g_rowptr[i + 1];
        float acc = g_h[(long)i * F_HID + tid];   // self-loop term (already dinv-scaled)
        for (int base = start; base < end; base += 256) {
            int m = min(256, end - base);
            __syncthreads();
            if (tid < m) jsm[tid] = g_adj[base + tid];
            __syncthreads();
            for (int t = 0; t < m; t++)
                acc += g_h[(long)jsm[t] * F_HID + tid];
        }
        float dv = g_dinv[i];
        float hr = fmaxf(fmaf(acc, dv, bias), 0.f);
        __syncthreads();
        hsm[tid] = hr;
        __syncthreads();

        // GEMM2: 8 warps x 5 outputs; lane l owns f = l, l+32, ..., l+224
        float hv[8];
#pragma unroll
        for (int k = 0; k < 8; k++) hv[k] = hsm[(k << 5) + lane];
#pragma unroll
        for (int oo = 0; oo < 5; oo++) {
            int o = w * 5 + oo;
            const float* wrow = &w2s[o * F_HID];
            float p = 0.f;
#pragma unroll
            for (int k = 0; k < 8; k++) p = fmaf(hv[k], wrow[(k << 5) + lane], p);
#pragma unroll
            for (int off = 16; off; off >>= 1)
                p += __shfl_xor_sync(0xffffffffu, p, off);
            if (lane == 0) g_h2[(long)i * F_OUT + o] = p * dv;  // pre-scale by dinv[i]
        }
    }
}

// ---------------- agg2 + bias + log_softmax ----------------
// warp per node; lane l owns feature l (and l+32 if l<8).
__global__ __launch_bounds__(256) void k_agg2(const float* __restrict__ b2,
                                              float* __restrict__ outF,
                                              float* __restrict__ outL,
                                              int n, int writeL) {
    int lane = threadIdx.x & 31;
    int wid  = (blockIdx.x * blockDim.x + threadIdx.x) >> 5;
    int nw   = (gridDim.x * blockDim.x) >> 5;
    float bias0 = b2[lane];
    float bias1 = (lane < 8) ? b2[32 + lane] : 0.f;

    for (int i = wid; i < n; i += nw) {
        int start = g_rowptr[i];
        int end   = g_rowptr[i + 1];
        long ib = (long)i * F_OUT;
        float a0 = g_h2[ib + lane];
        float a1 = (lane < 8) ? g_h2[ib + 32 + lane] : 0.f;
        for (int e = start; e < end; e++) {
            int j = g_adj[e];
            long jb = (long)j * F_OUT;
            a0 += g_h2[jb + lane];
            if (lane < 8) a1 += g_h2[jb + 32 + lane];
        }
        float dv = g_dinv[i];
        float f0 = fmaf(a0, dv, bias0);
        float f1 = (lane < 8) ? fmaf(a1, dv, bias1) : -INFINITY;
        outF[ib + lane] = f0;
        if (lane < 8) outF[ib + 32 + lane] = f1;

        if (writeL) {
            float mx = fmaxf(f0, f1);
#pragma unroll
            for (int off = 16; off; off >>= 1)
                mx = fmaxf(mx, __shfl_xor_sync(0xffffffffu, mx, off));
            float s = expf(f0 - mx) + ((lane < 8) ? expf(f1 - mx) : 0.f);
#pragma unroll
            for (int off = 16; off; off >>= 1)
                s += __shfl_xor_sync(0xffffffffu, s, off);
            float lse = mx + logf(s);
            outL[ib + lane] = f0 - lse;
            if (lane < 8) outL[ib + 32 + lane] = f1 - lse;
        }
    }
}

// ---------------- launch ----------------
extern "C" void kernel_launch(void* const* d_in, const int* in_sizes, int n_in,
                              void* d_out, int out_size) {
    const float* x  = (const float*)d_in[0];
    const void*  ei = d_in[1];
    const float* W1 = (const float*)d_in[2];
    const float* b1 = (const float*)d_in[3];
    const float* W2 = (const float*)d_in[4];
    const float* b2 = (const float*)d_in[5];

    int n = in_sizes[0] / F_IN;
    int E = in_sizes[1] / 2;

    float* out = (float*)d_out;
    int half = n * F_OUT;
    float* outF = out;
    float* outL = out;
    int writeL = 0;
    if (out_size >= 2 * half) { outL = out + half; writeL = 1; }

    int nb = (n + 1023) >> 10;

    k_init   <<<(n + 255) / 256, 256>>>(n);
    k_detect <<<1024, 256>>>((const long long*)ei, E, n);
    k_convert<<<2048, 256>>>(ei, E, n);
    k_hist   <<<2048, 256>>>(E);
    k_dinv   <<<(n + 255) / 256, 256>>>(n);
    k_scan1  <<<nb, 1024>>>(n);
    k_scan2  <<<1, 256>>>(nb);
    k_scan3  <<<(n + 255) / 256, 256>>>(n, E);
    k_fill   <<<2048, 256>>>(E);
    k_tw2    <<<(F_OUT * F_HID + 255) / 256, 256>>>(W2);

    dim3 g1(2, (n + 127) / 128);
    k_sgemm1<<<g1, 256>>>(x, W1, n);

    k_agg1<<<4096, 256>>>(b1, n);
    k_agg2<<<2048, 256>>>(b2, outF, outL, n, writeL);
}

// round 5
// speedup vs baseline: 1.3494x; 1.3494x over previous
#include <cuda_runtime.h>
#include <cuda_bf16.h>
#include <math.h>

// Problem constants (fixed by the reference)
#define F_IN   512
#define F_HID  256
#define F_OUT  40
#define MAXN   100000
#define MAXE   3200000

// ---------------- scratch (device globals; no runtime allocation) ----------------
__device__ int   g_is32;               // 1 if edge_index is int32, 0 if int64
__device__ int   g_eidx[2 * MAXE];     // converted edge list: [row(E), col(E)]
__device__ int   g_deg[MAXN];          // col-degree (init 1 for self-loop)
__device__ int   g_cnt[MAXN];          // row counts (for CSR)
__device__ float g_dinv[MAXN];
__device__ int   g_rowptr[MAXN + 1];
__device__ int   g_cursor[MAXN];
__device__ int   g_adj[MAXE];
__device__ int   g_part[256];
__device__ float g_w2t[F_OUT * F_HID]; // W2 transposed [o][f]
__device__ float g_h [(long)MAXN * F_HID];  // h_s = dinv[i] * (x @ W1)
__device__ float g_h2[(long)MAXN * F_OUT];  // h2_s = dinv[i] * (relu(...) @ W2)

// ---------------- dtype detect + convert ----------------
__global__ void k_init(int n) {
    int i = blockIdx.x * blockDim.x + threadIdx.x;
    if (i < n) { g_deg[i] = 1; g_cnt[i] = 0; }
    if (i == 0) g_is32 = 0;
}

// Read buffer as int64; any value outside [0, n) => data is really int32.
__global__ void k_detect(const long long* __restrict__ ei, int E, int n) {
    int bad = 0;
    for (long e = blockIdx.x * blockDim.x + threadIdx.x; e < (long)E; e += (long)gridDim.x * blockDim.x) {
        long long v = ei[e];
        if (v < 0 || v >= n) bad = 1;
    }
    if (__syncthreads_or(bad)) {
        if (threadIdx.x == 0) g_is32 = 1;
    }
}

__global__ void k_convert(const void* __restrict__ ei_raw, int E, int n) {
    int is32 = g_is32;
    const int*       e32 = (const int*)ei_raw;
    const long long* e64 = (const long long*)ei_raw;
    for (long e = blockIdx.x * blockDim.x + threadIdx.x; e < 2L * E; e += (long)gridDim.x * blockDim.x) {
        long long v = is32 ? (long long)e32[e] : e64[e];
        if (v < 0) v = 0;
        if (v >= n) v = n - 1;   // clamp: address-space safety (identity on valid data)
        g_eidx[e] = (int)v;
    }
}

// ---------------- degree / histogram ----------------
__global__ void k_hist(int E) {
    for (int e = blockIdx.x * blockDim.x + threadIdx.x; e < E; e += gridDim.x * blockDim.x) {
        int r = g_eidx[e];
        int c = g_eidx[E + e];
        atomicAdd(&g_deg[c], 1);
        atomicAdd(&g_cnt[r], 1);
    }
}

__global__ void k_dinv(int n) {
    int i = blockIdx.x * blockDim.x + threadIdx.x;
    if (i < n) g_dinv[i] = rsqrtf((float)g_deg[i]);
}

// ---------------- CSR build: scan over g_cnt ----------------
__global__ void k_scan1(int n) {
    __shared__ int s[1024];
    int tid = threadIdx.x;
    int idx = blockIdx.x * 1024 + tid;
    int v = (idx < n) ? g_cnt[idx] : 0;
    s[tid] = v;
    __syncthreads();
    for (int off = 1; off < 1024; off <<= 1) {
        int t = (tid >= off) ? s[tid - off] : 0;
        __syncthreads();
        s[tid] += t;
        __syncthreads();
    }
    if (idx < n) g_rowptr[idx] = s[tid] - v;   // local exclusive
    if (tid == 1023) g_part[blockIdx.x] = s[1023];
}

__global__ void k_scan2(int nb) {
    __shared__ int s[256];
    int tid = threadIdx.x;
    int v = (tid < nb) ? g_part[tid] : 0;
    s[tid] = v;
    __syncthreads();
    for (int off = 1; off < 256; off <<= 1) {
        int t = (tid >= off) ? s[tid - off] : 0;
        __syncthreads();
        s[tid] += t;
        __syncthreads();
    }
    if (tid < nb) g_part[tid] = s[tid] - v;    // exclusive
}

__global__ void k_scan3(int n, int E) {
    int i = blockIdx.x * blockDim.x + threadIdx.x;
    if (i < n) {
        int rp = g_rowptr[i] + g_part[i >> 10];
        g_rowptr[i] = rp;
        g_cursor[i] = rp;
    }
    if (blockIdx.x == 0 && threadIdx.x == 0) g_rowptr[n] = E;
}

__global__ void k_fill(int E) {
    for (int e = blockIdx.x * blockDim.x + threadIdx.x; e < E; e += gridDim.x * blockDim.x) {
        int r = g_eidx[e];
        int c = g_eidx[E + e];
        int pos = atomicAdd(&g_cursor[r], 1);
        g_adj[pos] = c;
    }
}

// ---------------- transpose W2 into [o][f] ----------------
__global__ void k_tw2(const float* __restrict__ W2) {
    int idx = blockIdx.x * blockDim.x + threadIdx.x;
    if (idx < F_OUT * F_HID) {
        int o = idx / F_HID, f = idx % F_HID;
        g_w2t[idx] = W2[f * F_OUT + o];
    }
}

// ---------------- tf32 tensor-core GEMM1 ----------------
// g_h[i][c] = dinv[i] * sum_k x[i][k] * W1[k][c],  M x 512 @ 512 x 256.
// 128x128 CTA tile, BK=16, double-buffered smem, 8 warps (64x32 each),
// mma.sync.m16n8k8.tf32.

__device__ __forceinline__ unsigned f2tf32(float x) {
    unsigned r;
    asm("cvt.rna.tf32.f32 %0, %1;" : "=r"(r) : "f"(x));
    return r;
}

__device__ __forceinline__ void mma8(float c[4], const unsigned a[4], const unsigned b[2]) {
    asm volatile(
        "mma.sync.aligned.m16n8k8.row.col.f32.tf32.tf32.f32 "
        "{%0,%1,%2,%3}, {%4,%5,%6,%7}, {%8,%9}, {%0,%1,%2,%3};"
        : "+f"(c[0]), "+f"(c[1]), "+f"(c[2]), "+f"(c[3])
        : "r"(a[0]), "r"(a[1]), "r"(a[2]), "r"(a[3]), "r"(b[0]), "r"(b[1]));
}

#define SPAD 136   // 128 + 8 pad: bank = (8k + idx) % 32 -> conflict-free frag reads

__global__ __launch_bounds__(256, 2) void k_gemm1_tf32(const float* __restrict__ A,
                                                       const float* __restrict__ B, int M) {
    __shared__ unsigned As[2][16][SPAD];
    __shared__ unsigned Bs[2][16][SPAD];

    const int tid  = threadIdx.x;
    const int lane = tid & 31;
    const int wid  = tid >> 5;
    const int wm   = wid & 1;     // 2 warp rows   (64 rows each)
    const int wn   = wid >> 1;    // 4 warp cols   (32 cols each)
    const int bx   = blockIdx.x;  // 0..1 (N blocks of 128)
    const long mBase = (long)blockIdx.y * 128;

    // A staging: thread -> row (tid&127), k-halfgroup (tid>>7)*8
    const int  rowA = tid & 127;
    const int  kcA  = (tid >> 7) * 8;
    const long gRowA = mBase + rowA;
    const bool okA   = gRowA < M;
    const float* Ag  = A + gRowA * F_IN;

    // B staging: thread -> k row (tid>>5, and +8), 4 cols at (tid&31)*4
    const int  krB  = tid >> 5;
    const int  colB = (tid & 31) * 4;
    const float* Bg = B + (long)bx * 128 + colB;

    float ra[8], rb[8];

    // ---- load k0 = 0 ----
    if (okA) {
        float4 t0 = *(const float4*)(Ag + kcA);
        float4 t1 = *(const float4*)(Ag + kcA + 4);
        ra[0]=t0.x; ra[1]=t0.y; ra[2]=t0.z; ra[3]=t0.w;
        ra[4]=t1.x; ra[5]=t1.y; ra[6]=t1.z; ra[7]=t1.w;
    } else {
#pragma unroll
        for (int j = 0; j < 8; j++) ra[j] = 0.f;
    }
    {
        float4 u0 = *(const float4*)(Bg + (long)krB * F_HID);
        float4 u1 = *(const float4*)(Bg + (long)(krB + 8) * F_HID);
        rb[0]=u0.x; rb[1]=u0.y; rb[2]=u0.z; rb[3]=u0.w;
        rb[4]=u1.x; rb[5]=u1.y; rb[6]=u1.z; rb[7]=u1.w;
    }
#pragma unroll
    for (int j = 0; j < 4; j++) {
        As[0][kcA + j][rowA]     = f2tf32(ra[j]);
        As[0][kcA + 4 + j][rowA] = f2tf32(ra[4 + j]);
    }
    {
        uint4 v0 = make_uint4(f2tf32(rb[0]), f2tf32(rb[1]), f2tf32(rb[2]), f2tf32(rb[3]));
        uint4 v1 = make_uint4(f2tf32(rb[4]), f2tf32(rb[5]), f2tf32(rb[6]), f2tf32(rb[7]));
        *(uint4*)&Bs[0][krB][colB]     = v0;
        *(uint4*)&Bs[0][krB + 8][colB] = v1;
    }
    __syncthreads();

    float c[4][4][4];
#pragma unroll
    for (int mt = 0; mt < 4; mt++)
#pragma unroll
        for (int nt = 0; nt < 4; nt++)
#pragma unroll
            for (int q = 0; q < 4; q++) c[mt][nt][q] = 0.f;

    int cur = 0;
    const int NITER = F_IN / 16;   // 32
    for (int it = 0; it < NITER; ++it) {
        if (it + 1 < NITER) {
            int k0n = (it + 1) * 16;
            if (okA) {
                float4 t0 = *(const float4*)(Ag + k0n + kcA);
                float4 t1 = *(const float4*)(Ag + k0n + kcA + 4);
                ra[0]=t0.x; ra[1]=t0.y; ra[2]=t0.z; ra[3]=t0.w;
                ra[4]=t1.x; ra[5]=t1.y; ra[6]=t1.z; ra[7]=t1.w;
            }
            float4 u0 = *(const float4*)(Bg + (long)(k0n + krB) * F_HID);
            float4 u1 = *(const float4*)(Bg + (long)(k0n + krB + 8) * F_HID);
            rb[0]=u0.x; rb[1]=u0.y; rb[2]=u0.z; rb[3]=u0.w;
            rb[4]=u1.x; rb[5]=u1.y; rb[6]=u1.z; rb[7]=u1.w;
        }

        // compute on buffer `cur` (two k8 steps)
#pragma unroll
        for (int kk = 0; kk < 16; kk += 8) {
            const int kq = kk + (lane & 3);
            const int p  = lane >> 2;
            unsigned afr[4][4], bfr[4][2];
#pragma unroll
            for (int mt = 0; mt < 4; mt++) {
                int r = wm * 64 + mt * 16 + p;
                afr[mt][0] = As[cur][kq][r];
                afr[mt][1] = As[cur][kq][r + 8];
                afr[mt][2] = As[cur][kq + 4][r];
                afr[mt][3] = As[cur][kq + 4][r + 8];
            }
#pragma unroll
            for (int nt = 0; nt < 4; nt++) {
                int cc = wn * 32 + nt * 8 + p;
                bfr[nt][0] = Bs[cur][kq][cc];
                bfr[nt][1] = Bs[cur][kq + 4][cc];
            }
#pragma unroll
            for (int mt = 0; mt < 4; mt++)
#pragma unroll
                for (int nt = 0; nt < 4; nt++)
                    mma8(c[mt][nt], afr[mt], bfr[nt]);
        }

        if (it + 1 < NITER) {
            int nxt = cur ^ 1;
#pragma unroll
            for (int j = 0; j < 4; j++) {
                As[nxt][kcA + j][rowA]     = f2tf32(ra[j]);
                As[nxt][kcA + 4 + j][rowA] = f2tf32(ra[4 + j]);
            }
            uint4 v0 = make_uint4(f2tf32(rb[0]), f2tf32(rb[1]), f2tf32(rb[2]), f2tf32(rb[3]));
            uint4 v1 = make_uint4(f2tf32(rb[4]), f2tf32(rb[5]), f2tf32(rb[6]), f2tf32(rb[7]));
            *(uint4*)&Bs[nxt][krB][colB]     = v0;
            *(uint4*)&Bs[nxt][krB + 8][colB] = v1;
            __syncthreads();
            cur = nxt;
        }
    }

    // ---- epilogue: scale by dinv[row], write g_h ----
    const int p = lane >> 2;
    const int q2 = (lane & 3) * 2;
#pragma unroll
    for (int mt = 0; mt < 4; mt++) {
        long r0 = mBase + wm * 64 + mt * 16 + p;
        long r1 = r0 + 8;
        if (r0 < M) {
            float dv = g_dinv[r0];
#pragma unroll
            for (int nt = 0; nt < 4; nt++) {
                long col = (long)bx * 128 + wn * 32 + nt * 8 + q2;
                float2 o = make_float2(c[mt][nt][0] * dv, c[mt][nt][1] * dv);
                *(float2*)(g_h + r0 * F_HID + col) = o;
            }
        }
        if (r1 < M) {
            float dv = g_dinv[r1];
#pragma unroll
            for (int nt = 0; nt < 4; nt++) {
                long col = (long)bx * 128 + wn * 32 + nt * 8 + q2;
                float2 o = make_float2(c[mt][nt][2] * dv, c[mt][nt][3] * dv);
                *(float2*)(g_h + r1 * F_HID + col) = o;
            }
        }
    }
}

// ---------------- agg1 + bias + relu + GEMM2 fused ----------------
// block of 256 threads per node (grid-stride). h fits in L2 -> gathers hit L2.
__global__ __launch_bounds__(256) void k_agg1(const float* __restrict__ b1, int n) {
    __shared__ float w2s[F_OUT * F_HID];   // 40 KB, loaded once per block
    __shared__ float hsm[F_HID];
    __shared__ int   jsm[256];
    int tid = threadIdx.x;
    for (int idx = tid; idx < F_OUT * F_HID; idx += 256) w2s[idx] = g_w2t[idx];
    __syncthreads();

    int lane = tid & 31, w = tid >> 5;
    float bias = b1[tid];

    for (int i = blockIdx.x; i < n; i += gridDim.x) {
        int start = g_rowptr[i];
        int end   = g_rowptr[i + 1];
        float acc = g_h[(long)i * F_HID + tid];   // self-loop term (already dinv-scaled)
        for (int base = start; base < end; base += 256) {
            int m = min(256, end - base);
            __syncthreads();
            if (tid < m) jsm[tid] = g_adj[base + tid];
            __syncthreads();
            for (int t = 0; t < m; t++)
                acc += g_h[(long)jsm[t] * F_HID + tid];
        }
        float dv = g_dinv[i];
        float hr = fmaxf(fmaf(acc, dv, bias), 0.f);
        __syncthreads();
        hsm[tid] = hr;
        __syncthreads();

        // GEMM2: 8 warps x 5 outputs; lane l owns f = l, l+32, ..., l+224
        float hv[8];
#pragma unroll
        for (int k = 0; k < 8; k++) hv[k] = hsm[(k << 5) + lane];
#pragma unroll
        for (int oo = 0; oo < 5; oo++) {
            int o = w * 5 + oo;
            const float* wrow = &w2s[o * F_HID];
            float p = 0.f;
#pragma unroll
            for (int k = 0; k < 8; k++) p = fmaf(hv[k], wrow[(k << 5) + lane], p);
#pragma unroll
            for (int off = 16; off; off >>= 1)
                p += __shfl_xor_sync(0xffffffffu, p, off);
            if (lane == 0) g_h2[(long)i * F_OUT + o] = p * dv;  // pre-scale by dinv[i]
        }
    }
}

// ---------------- agg2 + bias + log_softmax ----------------
// warp per node; lane l owns feature l (and l+32 if l<8).
__global__ __launch_bounds__(256) void k_agg2(const float* __restrict__ b2,
                                              float* __restrict__ outF,
                                              float* __restrict__ outL,
                                              int n, int writeL) {
    int lane = threadIdx.x & 31;
    int wid  = (blockIdx.x * blockDim.x + threadIdx.x) >> 5;
    int nw   = (gridDim.x * blockDim.x) >> 5;
    float bias0 = b2[lane];
    float bias1 = (lane < 8) ? b2[32 + lane] : 0.f;

    for (int i = wid; i < n; i += nw) {
        int start = g_rowptr[i];
        int end   = g_rowptr[i + 1];
        long ib = (long)i * F_OUT;
        float a0 = g_h2[ib + lane];
        float a1 = (lane < 8) ? g_h2[ib + 32 + lane] : 0.f;
        for (int e = start; e < end; e++) {
            int j = g_adj[e];
            long jb = (long)j * F_OUT;
            a0 += g_h2[jb + lane];
            if (lane < 8) a1 += g_h2[jb + 32 + lane];
        }
        float dv = g_dinv[i];
        float f0 = fmaf(a0, dv, bias0);
        float f1 = (lane < 8) ? fmaf(a1, dv, bias1) : -INFINITY;
        outF[ib + lane] = f0;
        if (lane < 8) outF[ib + 32 + lane] = f1;

        if (writeL) {
            float mx = fmaxf(f0, f1);
#pragma unroll
            for (int off = 16; off; off >>= 1)
                mx = fmaxf(mx, __shfl_xor_sync(0xffffffffu, mx, off));
            float s = expf(f0 - mx) + ((lane < 8) ? expf(f1 - mx) : 0.f);
#pragma unroll
            for (int off = 16; off; off >>= 1)
                s += __shfl_xor_sync(0xffffffffu, s, off);
            float lse = mx + logf(s);
            outL[ib + lane] = f0 - lse;
            if (lane < 8) outL[ib + 32 + lane] = f1 - lse;
        }
    }
}

// ---------------- launch ----------------
extern "C" void kernel_launch(void* const* d_in, const int* in_sizes, int n_in,
                              void* d_out, int out_size) {
    const float* x  = (const float*)d_in[0];
    const void*  ei = d_in[1];
    const float* W1 = (const float*)d_in[2];
    const float* b1 = (const float*)d_in[3];
    const float* W2 = (const float*)d_in[4];
    const float* b2 = (const float*)d_in[5];

    int n = in_sizes[0] / F_IN;
    int E = in_sizes[1] / 2;

    float* out = (float*)d_out;
    int half = n * F_OUT;
    float* outF = out;
    float* outL = out;
    int writeL = 0;
    if (out_size >= 2 * half) { outL = out + half; writeL = 1; }

    int nb = (n + 1023) >> 10;

    k_init   <<<(n + 255) / 256, 256>>>(n);
    k_detect <<<1024, 256>>>((const long long*)ei, E, n);
    k_convert<<<2048, 256>>>(ei, E, n);
    k_hist   <<<2048, 256>>>(E);
    k_dinv   <<<(n + 255) / 256, 256>>>(n);
    k_scan1  <<<nb, 1024>>>(n);
    k_scan2  <<<1, 256>>>(nb);
    k_scan3  <<<(n + 255) / 256, 256>>>(n, E);
    k_fill   <<<2048, 256>>>(E);
    k_tw2    <<<(F_OUT * F_HID + 255) / 256, 256>>>(W2);

    dim3 g1(2, (n + 127) / 128);
    k_gemm1_tf32<<<g1, 256>>>(x, W1, n);

    k_agg1<<<4096, 256>>>(b1, n);
    k_agg2<<<2048, 256>>>(b2, outF, outL, n, writeL);
}

// round 8
// speedup vs baseline: 1.4498x; 1.0743x over previous
#include <cuda_runtime.h>
#include <cuda_bf16.h>
#include <cuda_fp16.h>
#include <stdint.h>
#include <math.h>

// Problem constants (fixed by the reference)
#define F_IN   512
#define F_HID  256
#define F_OUT  40
#define MAXN   100000
#define MAXE   3200000

// ---------------- scratch (device globals; no runtime allocation) ----------------
__device__ int   g_is32;
__device__ int   g_eidx[2 * MAXE];
__device__ int   g_deg[MAXN];
__device__ int   g_cnt[MAXN];
__device__ float g_dinv[MAXN];
__device__ int   g_rowptr[MAXN + 1];
__device__ int   g_cursor[MAXN];
__device__ int   g_adj[MAXE];
__device__ int   g_part[256];
__device__ float g_w2t[F_OUT * F_HID];
__device__ unsigned g_w1p[(F_IN / 2) * F_HID];  // W1 packed half2 along k: [k2][n]
__device__ float g_h [(long)MAXN * F_HID];      // h_s = dinv[i] * (x @ W1)
__device__ float g_h2[(long)MAXN * F_OUT];      // h2_s = dinv[i] * (relu(...) @ W2)

// ---------------- dtype detect + convert (+ fused histogram) ----------------
__global__ void k_init(int n) {
    int i = blockIdx.x * blockDim.x + threadIdx.x;
    if (i < n) { g_deg[i] = 1; g_cnt[i] = 0; }
    if (i == 0) g_is32 = 0;
}

__global__ void k_detect(const long long* __restrict__ ei, int E, int n) {
    int bad = 0;
    for (long e = blockIdx.x * blockDim.x + threadIdx.x; e < (long)E; e += (long)gridDim.x * blockDim.x) {
        long long v = ei[e];
        if (v < 0 || v >= n) bad = 1;
    }
    if (__syncthreads_or(bad)) {
        if (threadIdx.x == 0) g_is32 = 1;
    }
}

__global__ void k_convert(const void* __restrict__ ei_raw, int E, int n) {
    int is32 = g_is32;
    const int*       e32 = (const int*)ei_raw;
    const long long* e64 = (const long long*)ei_raw;
    for (long e = blockIdx.x * blockDim.x + threadIdx.x; e < 2L * E; e += (long)gridDim.x * blockDim.x) {
        long long v = is32 ? (long long)e32[e] : e64[e];
        if (v < 0) v = 0;
        if (v >= n) v = n - 1;
        int vi = (int)v;
        g_eidx[e] = vi;
        if (e < E) atomicAdd(&g_cnt[vi], 1);   // row counts
        else       atomicAdd(&g_deg[vi], 1);   // col degrees
    }
}

__global__ void k_dinv(int n) {
    int i = blockIdx.x * blockDim.x + threadIdx.x;
    if (i < n) g_dinv[i] = rsqrtf((float)g_deg[i]);
}

// ---------------- CSR build ----------------
__global__ void k_scan1(int n) {
    __shared__ int s[1024];
    int tid = threadIdx.x;
    int idx = blockIdx.x * 1024 + tid;
    int v = (idx < n) ? g_cnt[idx] : 0;
    s[tid] = v;
    __syncthreads();
    for (int off = 1; off < 1024; off <<= 1) {
        int t = (tid >= off) ? s[tid - off] : 0;
        __syncthreads();
        s[tid] += t;
        __syncthreads();
    }
    if (idx < n) g_rowptr[idx] = s[tid] - v;
    if (tid == 1023) g_part[blockIdx.x] = s[1023];
}

__global__ void k_scan2(int nb) {
    __shared__ int s[256];
    int tid = threadIdx.x;
    int v = (tid < nb) ? g_part[tid] : 0;
    s[tid] = v;
    __syncthreads();
    for (int off = 1; off < 256; off <<= 1) {
        int t = (tid >= off) ? s[tid - off] : 0;
        __syncthreads();
        s[tid] += t;
        __syncthreads();
    }
    if (tid < nb) g_part[tid] = s[tid] - v;
}

__global__ void k_scan3(int n, int E) {
    int i = blockIdx.x * blockDim.x + threadIdx.x;
    if (i < n) {
        int rp = g_rowptr[i] + g_part[i >> 10];
        g_rowptr[i] = rp;
        g_cursor[i] = rp;
    }
    if (blockIdx.x == 0 && threadIdx.x == 0) g_rowptr[n] = E;
}

__global__ void k_fill(int E) {
    for (int e = blockIdx.x * blockDim.x + threadIdx.x; e < E; e += gridDim.x * blockDim.x) {
        int r = g_eidx[e];
        int c = g_eidx[E + e];
        int pos = atomicAdd(&g_cursor[r], 1);
        g_adj[pos] = c;
    }
}

// ---------------- weight prep ----------------
__global__ void k_tw2(const float* __restrict__ W2) {
    int idx = blockIdx.x * blockDim.x + threadIdx.x;
    if (idx < F_OUT * F_HID) {
        int o = idx / F_HID, f = idx % F_HID;
        g_w2t[idx] = W2[f * F_OUT + o];
    }
}

// W1 [512][256] fp32 -> packed half2 along k: g_w1p[k2*256 + n] = half2(W1[2k2][n], W1[2k2+1][n])
__global__ void k_tw1p(const float* __restrict__ W1) {
    int idx = blockIdx.x * blockDim.x + threadIdx.x;
    if (idx < (F_IN / 2) * F_HID) {
        int k2 = idx >> 8;
        int nn = idx & 255;
        __half2 h = __floats2half2_rn(W1[(2 * k2) * F_HID + nn], W1[(2 * k2 + 1) * F_HID + nn]);
        g_w1p[idx] = *(unsigned*)&h;
    }
}

// ---------------- fp16 tensor-core GEMM1 (mma.sync.m16n8k16) ----------------
// g_h[i][c] = dinv[i] * sum_k x[i][k] * W1[k][c],  M x 512 @ 512 x 256.
// 128x128 CTA tile, BK=32 (two k16 steps), double-buffered smem, 8 warps (64x32 each).

__device__ __forceinline__ void mma16(float c[4], const unsigned a[4], const unsigned b[2]) {
    asm volatile(
        "mma.sync.aligned.m16n8k16.row.col.f32.f16.f16.f32 "
        "{%0,%1,%2,%3}, {%4,%5,%6,%7}, {%8,%9}, {%0,%1,%2,%3};"
        : "+f"(c[0]), "+f"(c[1]), "+f"(c[2]), "+f"(c[3])
        : "r"(a[0]), "r"(a[1]), "r"(a[2]), "r"(a[3]), "r"(b[0]), "r"(b[1]));
}

__device__ __forceinline__ unsigned packh2(float lo, float hi) {
    __half2 h = __floats2half2_rn(lo, hi);
    return *(unsigned*)&h;
}

#define SPAD 136   // bank = (8*k2 + idx) % 32 -> conflict-free frag reads

__global__ __launch_bounds__(256, 2) void k_gemm1_h(const float* __restrict__ A, int M) {
    __shared__ unsigned As2[2][16][SPAD];   // [k2 within BK=32][row]
    __shared__ unsigned Bs2[2][16][SPAD];   // [k2][col]

    const int tid  = threadIdx.x;
    const int lane = tid & 31;
    const int wid  = tid >> 5;
    const int wm   = wid & 1;     // 2 warp rows (64 rows each)
    const int wn   = wid >> 1;    // 4 warp cols (32 cols each)
    const int bx   = blockIdx.x;  // 0..1
    const long mBase = (long)blockIdx.y * 128;

    // A staging: row = tid&127, 16-float k-slab = (tid>>7)*16
    const int  rowA = tid & 127;
    const int  kfA  = (tid >> 7) * 16;   // float offset within BK=32
    const int  k2A  = kfA >> 1;          // half2 row base (0 or 8)
    const long gRowA = mBase + rowA;
    const bool okA   = gRowA < M;
    const float* Ag  = A + gRowA * F_IN + kfA;

    // B staging: k2 row = tid>>4 (16 rows), cols = (tid&15)*8
    const int krB  = tid >> 4;
    const int colB = (tid & 15) * 8;
    const unsigned* Wp = g_w1p + (long)bx * 128 + colB;

    float fa[16];
    uint4 ub0, ub1;

    // ---- load chunk 0 ----
    if (okA) {
#pragma unroll
        for (int j = 0; j < 4; j++) *(float4*)&fa[j * 4] = *(const float4*)(Ag + j * 4);
    } else {
#pragma unroll
        for (int j = 0; j < 16; j++) fa[j] = 0.f;
    }
    ub0 = *(const uint4*)(Wp + (long)krB * F_HID);
    ub1 = *(const uint4*)(Wp + (long)krB * F_HID + 4);

#pragma unroll
    for (int j = 0; j < 8; j++) As2[0][k2A + j][rowA] = packh2(fa[2 * j], fa[2 * j + 1]);
    *(uint4*)&Bs2[0][krB][colB]     = ub0;
    *(uint4*)&Bs2[0][krB][colB + 4] = ub1;
    __syncthreads();

    float c[4][4][4];
#pragma unroll
    for (int mt = 0; mt < 4; mt++)
#pragma unroll
        for (int nt = 0; nt < 4; nt++)
#pragma unroll
            for (int q = 0; q < 4; q++) c[mt][nt][q] = 0.f;

    int cur = 0;
    const int NITER = F_IN / 32;   // 16
    for (int it = 0; it < NITER; ++it) {
        if (it + 1 < NITER) {
            int kf = (it + 1) * 32;
            if (okA) {
#pragma unroll
                for (int j = 0; j < 4; j++) *(float4*)&fa[j * 4] = *(const float4*)(Ag + kf + j * 4);
            }
            ub0 = *(const uint4*)(Wp + (long)(kf / 2 + krB) * F_HID);
            ub1 = *(const uint4*)(Wp + (long)(kf / 2 + krB) * F_HID + 4);
        }

        // compute on buffer `cur`: two k16 steps (k2 halves 0..7 and 8..15)
#pragma unroll
        for (int kk = 0; kk < 16; kk += 8) {
            const int k2q = kk + (lane & 3);
            const int p   = lane >> 2;
            unsigned afr[4][4], bfr[4][2];
#pragma unroll
            for (int mt = 0; mt < 4; mt++) {
                int r = wm * 64 + mt * 16 + p;
                afr[mt][0] = As2[cur][k2q][r];
                afr[mt][1] = As2[cur][k2q][r + 8];
                afr[mt][2] = As2[cur][k2q + 4][r];
                afr[mt][3] = As2[cur][k2q + 4][r + 8];
            }
#pragma unroll
            for (int nt = 0; nt < 4; nt++) {
                int cc = wn * 32 + nt * 8 + p;
                bfr[nt][0] = Bs2[cur][k2q][cc];
                bfr[nt][1] = Bs2[cur][k2q + 4][cc];
            }
#pragma unroll
            for (int mt = 0; mt < 4; mt++)
#pragma unroll
                for (int nt = 0; nt < 4; nt++)
                    mma16(c[mt][nt], afr[mt], bfr[nt]);
        }

        if (it + 1 < NITER) {
            int nxt = cur ^ 1;
#pragma unroll
            for (int j = 0; j < 8; j++) As2[nxt][k2A + j][rowA] = packh2(fa[2 * j], fa[2 * j + 1]);
            *(uint4*)&Bs2[nxt][krB][colB]     = ub0;
            *(uint4*)&Bs2[nxt][krB][colB + 4] = ub1;
            __syncthreads();
            cur = nxt;
        }
    }

    // ---- epilogue: scale by dinv[row], write g_h ----
    const int p  = lane >> 2;
    const int q2 = (lane & 3) * 2;
#pragma unroll
    for (int mt = 0; mt < 4; mt++) {
        long r0 = mBase + wm * 64 + mt * 16 + p;
        long r1 = r0 + 8;
        if (r0 < M) {
            float dv = g_dinv[r0];
#pragma unroll
            for (int nt = 0; nt < 4; nt++) {
                long col = (long)bx * 128 + wn * 32 + nt * 8 + q2;
                float2 o = make_float2(c[mt][nt][0] * dv, c[mt][nt][1] * dv);
                *(float2*)(g_h + r0 * F_HID + col) = o;
            }
        }
        if (r1 < M) {
            float dv = g_dinv[r1];
#pragma unroll
            for (int nt = 0; nt < 4; nt++) {
                long col = (long)bx * 128 + wn * 32 + nt * 8 + q2;
                float2 o = make_float2(c[mt][nt][2] * dv, c[mt][nt][3] * dv);
                *(float2*)(g_h + r1 * F_HID + col) = o;
            }
        }
    }
}

// ---------------- agg1 + bias + relu + GEMM2 fused ----------------
__global__ __launch_bounds__(256) void k_agg1(const float* __restrict__ b1, int n) {
    __shared__ float w2s[F_OUT * F_HID];
    __shared__ float hsm[F_HID];
    __shared__ int   jsm[256];
    int tid = threadIdx.x;
    for (int idx = tid; idx < F_OUT * F_HID; idx += 256) w2s[idx] = g_w2t[idx];
    __syncthreads();

    int lane = tid & 31, w = tid >> 5;
    float bias = b1[tid];

    for (int i = blockIdx.x; i < n; i += gridDim.x) {
        int start = g_rowptr[i];
        int end   = g_rowptr[i + 1];
        float acc = g_h[(long)i * F_HID + tid];
        for (int base = start; base < end; base += 256) {
            int m = min(256, end - base);
            __syncthreads();
            if (tid < m) jsm[tid] = g_adj[base + tid];
            __syncthreads();
            for (int t = 0; t < m; t++)
                acc += g_h[(long)jsm[t] * F_HID + tid];
        }
        float dv = g_dinv[i];
        float hr = fmaxf(fmaf(acc, dv, bias), 0.f);
        __syncthreads();
        hsm[tid] = hr;
        __syncthreads();

        float hv[8];
#pragma unroll
        for (int k = 0; k < 8; k++) hv[k] = hsm[(k << 5) + lane];
#pragma unroll
        for (int oo = 0; oo < 5; oo++) {
            int o = w * 5 + oo;
            const float* wrow = &w2s[o * F_HID];
            float p = 0.f;
#pragma unroll
            for (int k = 0; k < 8; k++) p = fmaf(hv[k], wrow[(k << 5) + lane], p);
#pragma unroll
            for (int off = 16; off; off >>= 1)
                p += __shfl_xor_sync(0xffffffffu, p, off);
            if (lane == 0) g_h2[(long)i * F_OUT + o] = p * dv;
        }
    }
}

// ---------------- agg2 + bias + log_softmax ----------------
__global__ __launch_bounds__(256) void k_agg2(const float* __restrict__ b2,
                                              float* __restrict__ outF,
                                              float* __restrict__ outL,
                                              int n, int writeL) {
    int lane = threadIdx.x & 31;
    int wid  = (blockIdx.x * blockDim.x + threadIdx.x) >> 5;
    int nw   = (gridDim.x * blockDim.x) >> 5;
    float bias0 = b2[lane];
    float bias1 = (lane < 8) ? b2[32 + lane] : 0.f;

    for (int i = wid; i < n; i += nw) {
        int start = g_rowptr[i];
        int end   = g_rowptr[i + 1];
        long ib = (long)i * F_OUT;
        float a0 = g_h2[ib + lane];
        float a1 = (lane < 8) ? g_h2[ib + 32 + lane] : 0.f;
        for (int e = start; e < end; e++) {
            int j = g_adj[e];
            long jb = (long)j * F_OUT;
            a0 += g_h2[jb + lane];
            if (lane < 8) a1 += g_h2[jb + 32 + lane];
        }
        float dv = g_dinv[i];
        float f0 = fmaf(a0, dv, bias0);
        float f1 = (lane < 8) ? fmaf(a1, dv, bias1) : -INFINITY;
        outF[ib + lane] = f0;
        if (lane < 8) outF[ib + 32 + lane] = f1;

        if (writeL) {
            float mx = fmaxf(f0, f1);
#pragma unroll
            for (int off = 16; off; off >>= 1)
                mx = fmaxf(mx, __shfl_xor_sync(0xffffffffu, mx, off));
            float s = expf(f0 - mx) + ((lane < 8) ? expf(f1 - mx) : 0.f);
#pragma unroll
            for (int off = 16; off; off >>= 1)
                s += __shfl_xor_sync(0xffffffffu, s, off);
            float lse = mx + logf(s);
            outL[ib + lane] = f0 - lse;
            if (lane < 8) outL[ib + 32 + lane] = f1 - lse;
        }
    }
}

// ---------------- launch ----------------
extern "C" void kernel_launch(void* const* d_in, const int* in_sizes, int n_in,
                              void* d_out, int out_size) {
    const float* x  = (const float*)d_in[0];
    const void*  ei = d_in[1];
    const float* W1 = (const float*)d_in[2];
    const float* b1 = (const float*)d_in[3];
    const float* W2 = (const float*)d_in[4];
    const float* b2 = (const float*)d_in[5];

    int n = in_sizes[0] / F_IN;
    int E = in_sizes[1] / 2;

    float* out = (float*)d_out;
    int half = n * F_OUT;
    float* outF = out;
    float* outL = out;
    int writeL = 0;
    if (out_size >= 2 * half) { outL = out + half; writeL = 1; }

    int nb = (n + 1023) >> 10;

    k_init   <<<(n + 255) / 256, 256>>>(n);
    k_detect <<<1024, 256>>>((const long long*)ei, E, n);
    k_convert<<<2048, 256>>>(ei, E, n);
    k_dinv   <<<(n + 255) / 256, 256>>>(n);
    k_scan1  <<<nb, 1024>>>(n);
    k_scan2  <<<1, 256>>>(nb);
    k_scan3  <<<(n + 255) / 256, 256>>>(n, E);
    k_fill   <<<2048, 256>>>(E);
    k_tw2    <<<(F_OUT * F_HID + 255) / 256, 256>>>(W2);
    k_tw1p   <<<((F_IN / 2) * F_HID + 255) / 256, 256>>>(W1);

    dim3 g1(2, (n + 127) / 128);
    k_gemm1_h<<<g1, 256>>>(x, n);

    k_agg1<<<4096, 256>>>(b1, n);
    k_agg2<<<2048, 256>>>(b2, outF, outL, n, writeL);
}

// round 9
// speedup vs baseline: 1.7074x; 1.1777x over previous
#include <cuda_runtime.h>
#include <cuda_bf16.h>
#include <cuda_fp16.h>
#include <stdint.h>
#include <math.h>

// Problem constants (fixed by the reference)
#define F_IN   512
#define F_HID  256
#define F_OUT  40
#define MAXN   100000
#define MAXE   3200000

// ---------------- scratch (device globals; no runtime allocation) ----------------
__device__ int   g_is32;
__device__ int   g_eidx[2 * MAXE];
__device__ int   g_deg[MAXN];
__device__ int   g_cnt[MAXN];
__device__ float g_dinv[MAXN];
__device__ int   g_rowptr[MAXN + 1];
__device__ int   g_cursor[MAXN];
__device__ int   g_adj[MAXE];
__device__ int   g_part[256];
__device__ float g_w2t[F_OUT * F_HID];
__device__ unsigned g_w1p[(F_IN / 2) * F_HID];   // W1 packed half2 along k: [k2][n]
__device__ unsigned g_hh[(long)MAXN * (F_HID/2)];// h_s = dinv[i]*(x@W1), half2-packed pairs
__device__ float g_h2[(long)MAXN * F_OUT];       // h2_s = dinv[i] * (relu(...) @ W2)

// ---------------- dtype detect + convert (+ fused histogram) ----------------
__global__ void k_init(int n) {
    int i = blockIdx.x * blockDim.x + threadIdx.x;
    if (i < n) { g_deg[i] = 1; g_cnt[i] = 0; }
    if (i == 0) g_is32 = 0;
}

__global__ void k_detect(const long long* __restrict__ ei, int E, int n) {
    int bad = 0;
    for (long e = blockIdx.x * blockDim.x + threadIdx.x; e < (long)E; e += (long)gridDim.x * blockDim.x) {
        long long v = ei[e];
        if (v < 0 || v >= n) bad = 1;
    }
    if (__syncthreads_or(bad)) {
        if (threadIdx.x == 0) g_is32 = 1;
    }
}

__global__ void k_convert(const void* __restrict__ ei_raw, int E, int n) {
    int is32 = g_is32;
    const int*       e32 = (const int*)ei_raw;
    const long long* e64 = (const long long*)ei_raw;
    for (long e = blockIdx.x * blockDim.x + threadIdx.x; e < 2L * E; e += (long)gridDim.x * blockDim.x) {
        long long v = is32 ? (long long)e32[e] : e64[e];
        if (v < 0) v = 0;
        if (v >= n) v = n - 1;
        int vi = (int)v;
        g_eidx[e] = vi;
        if (e < E) atomicAdd(&g_cnt[vi], 1);   // row counts
        else       atomicAdd(&g_deg[vi], 1);   // col degrees
    }
}

__global__ void k_dinv(int n) {
    int i = blockIdx.x * blockDim.x + threadIdx.x;
    if (i < n) g_dinv[i] = rsqrtf((float)g_deg[i]);
}

// ---------------- CSR build ----------------
__global__ void k_scan1(int n) {
    __shared__ int s[1024];
    int tid = threadIdx.x;
    int idx = blockIdx.x * 1024 + tid;
    int v = (idx < n) ? g_cnt[idx] : 0;
    s[tid] = v;
    __syncthreads();
    for (int off = 1; off < 1024; off <<= 1) {
        int t = (tid >= off) ? s[tid - off] : 0;
        __syncthreads();
        s[tid] += t;
        __syncthreads();
    }
    if (idx < n) g_rowptr[idx] = s[tid] - v;
    if (tid == 1023) g_part[blockIdx.x] = s[1023];
}

__global__ void k_scan2(int nb) {
    __shared__ int s[256];
    int tid = threadIdx.x;
    int v = (tid < nb) ? g_part[tid] : 0;
    s[tid] = v;
    __syncthreads();
    for (int off = 1; off < 256; off <<= 1) {
        int t = (tid >= off) ? s[tid - off] : 0;
        __syncthreads();
        s[tid] += t;
        __syncthreads();
    }
    if (tid < nb) g_part[tid] = s[tid] - v;
}

__global__ void k_scan3(int n, int E) {
    int i = blockIdx.x * blockDim.x + threadIdx.x;
    if (i < n) {
        int rp = g_rowptr[i] + g_part[i >> 10];
        g_rowptr[i] = rp;
        g_cursor[i] = rp;
    }
    if (blockIdx.x == 0 && threadIdx.x == 0) g_rowptr[n] = E;
}

__global__ void k_fill(int E) {
    for (int e = blockIdx.x * blockDim.x + threadIdx.x; e < E; e += gridDim.x * blockDim.x) {
        int r = g_eidx[e];
        int c = g_eidx[E + e];
        int pos = atomicAdd(&g_cursor[r], 1);
        g_adj[pos] = c;
    }
}

// ---------------- weight prep ----------------
__global__ void k_tw2(const float* __restrict__ W2) {
    int idx = blockIdx.x * blockDim.x + threadIdx.x;
    if (idx < F_OUT * F_HID) {
        int o = idx / F_HID, f = idx % F_HID;
        g_w2t[idx] = W2[f * F_OUT + o];
    }
}

// W1 [512][256] fp32 -> packed half2 along k: g_w1p[k2*256 + n] = half2(W1[2k2][n], W1[2k2+1][n])
__global__ void k_tw1p(const float* __restrict__ W1) {
    int idx = blockIdx.x * blockDim.x + threadIdx.x;
    if (idx < (F_IN / 2) * F_HID) {
        int k2 = idx >> 8;
        int nn = idx & 255;
        __half2 h = __floats2half2_rn(W1[(2 * k2) * F_HID + nn], W1[(2 * k2 + 1) * F_HID + nn]);
        g_w1p[idx] = *(unsigned*)&h;
    }
}

// ---------------- fp16 tensor-core GEMM1 (mma.sync.m16n8k16) ----------------
// g_hh[i][c2] = half2( dinv[i] * sum_k x[i][k]*W1[k][2c2], ..., [2c2+1] )
// 128x128 CTA tile, BK=32 (two k16 steps), double-buffered smem, 8 warps (64x32 each).

__device__ __forceinline__ void mma16(float c[4], const unsigned a[4], const unsigned b[2]) {
    asm volatile(
        "mma.sync.aligned.m16n8k16.row.col.f32.f16.f16.f32 "
        "{%0,%1,%2,%3}, {%4,%5,%6,%7}, {%8,%9}, {%0,%1,%2,%3};"
        : "+f"(c[0]), "+f"(c[1]), "+f"(c[2]), "+f"(c[3])
        : "r"(a[0]), "r"(a[1]), "r"(a[2]), "r"(a[3]), "r"(b[0]), "r"(b[1]));
}

__device__ __forceinline__ unsigned packh2(float lo, float hi) {
    __half2 h = __floats2half2_rn(lo, hi);
    return *(unsigned*)&h;
}

#define SPAD 136   // bank = (8*k2 + idx) % 32 -> conflict-free frag reads

__global__ __launch_bounds__(256, 2) void k_gemm1_h(const float* __restrict__ A, int M) {
    __shared__ unsigned As2[2][16][SPAD];   // [k2 within BK=32][row]
    __shared__ unsigned Bs2[2][16][SPAD];   // [k2][col]

    const int tid  = threadIdx.x;
    const int lane = tid & 31;
    const int wid  = tid >> 5;
    const int wm   = wid & 1;     // 2 warp rows (64 rows each)
    const int wn   = wid >> 1;    // 4 warp cols (32 cols each)
    const int bx   = blockIdx.x;  // 0..1
    const long mBase = (long)blockIdx.y * 128;

    // A staging: row = tid&127, 16-float k-slab = (tid>>7)*16
    const int  rowA = tid & 127;
    const int  kfA  = (tid >> 7) * 16;
    const int  k2A  = kfA >> 1;
    const long gRowA = mBase + rowA;
    const bool okA   = gRowA < M;
    const float* Ag  = A + gRowA * F_IN + kfA;

    // B staging: k2 row = tid>>4 (16 rows), cols = (tid&15)*8
    const int krB  = tid >> 4;
    const int colB = (tid & 15) * 8;
    const unsigned* Wp = g_w1p + (long)bx * 128 + colB;

    float fa[16];
    uint4 ub0, ub1;

    if (okA) {
#pragma unroll
        for (int j = 0; j < 4; j++) *(float4*)&fa[j * 4] = *(const float4*)(Ag + j * 4);
    } else {
#pragma unroll
        for (int j = 0; j < 16; j++) fa[j] = 0.f;
    }
    ub0 = *(const uint4*)(Wp + (long)krB * F_HID);
    ub1 = *(const uint4*)(Wp + (long)krB * F_HID + 4);

#pragma unroll
    for (int j = 0; j < 8; j++) As2[0][k2A + j][rowA] = packh2(fa[2 * j], fa[2 * j + 1]);
    *(uint4*)&Bs2[0][krB][colB]     = ub0;
    *(uint4*)&Bs2[0][krB][colB + 4] = ub1;
    __syncthreads();

    float c[4][4][4];
#pragma unroll
    for (int mt = 0; mt < 4; mt++)
#pragma unroll
        for (int nt = 0; nt < 4; nt++)
#pragma unroll
            for (int q = 0; q < 4; q++) c[mt][nt][q] = 0.f;

    int cur = 0;
    const int NITER = F_IN / 32;   // 16
    for (int it = 0; it < NITER; ++it) {
        if (it + 1 < NITER) {
            int kf = (it + 1) * 32;
            if (okA) {
#pragma unroll
                for (int j = 0; j < 4; j++) *(float4*)&fa[j * 4] = *(const float4*)(Ag + kf + j * 4);
            }
            ub0 = *(const uint4*)(Wp + (long)(kf / 2 + krB) * F_HID);
            ub1 = *(const uint4*)(Wp + (long)(kf / 2 + krB) * F_HID + 4);
        }

#pragma unroll
        for (int kk = 0; kk < 16; kk += 8) {
            const int k2q = kk + (lane & 3);
            const int p   = lane >> 2;
            unsigned afr[4][4], bfr[4][2];
#pragma unroll
            for (int mt = 0; mt < 4; mt++) {
                int r = wm * 64 + mt * 16 + p;
                afr[mt][0] = As2[cur][k2q][r];
                afr[mt][1] = As2[cur][k2q][r + 8];
                afr[mt][2] = As2[cur][k2q + 4][r];
                afr[mt][3] = As2[cur][k2q + 4][r + 8];
            }
#pragma unroll
            for (int nt = 0; nt < 4; nt++) {
                int cc = wn * 32 + nt * 8 + p;
                bfr[nt][0] = Bs2[cur][k2q][cc];
                bfr[nt][1] = Bs2[cur][k2q + 4][cc];
            }
#pragma unroll
            for (int mt = 0; mt < 4; mt++)
#pragma unroll
                for (int nt = 0; nt < 4; nt++)
                    mma16(c[mt][nt], afr[mt], bfr[nt]);
        }

        if (it + 1 < NITER) {
            int nxt = cur ^ 1;
#pragma unroll
            for (int j = 0; j < 8; j++) As2[nxt][k2A + j][rowA] = packh2(fa[2 * j], fa[2 * j + 1]);
            *(uint4*)&Bs2[nxt][krB][colB]     = ub0;
            *(uint4*)&Bs2[nxt][krB][colB + 4] = ub1;
            __syncthreads();
            cur = nxt;
        }
    }

    // ---- epilogue: scale by dinv[row], pack to half2, write g_hh ----
    const int p  = lane >> 2;
    const int q2 = (lane & 3) * 2;
#pragma unroll
    for (int mt = 0; mt < 4; mt++) {
        long r0 = mBase + wm * 64 + mt * 16 + p;
        long r1 = r0 + 8;
        if (r0 < M) {
            float dv = g_dinv[r0];
#pragma unroll
            for (int nt = 0; nt < 4; nt++) {
                int col = bx * 128 + wn * 32 + nt * 8 + q2;
                g_hh[r0 * (F_HID/2) + (col >> 1)] = packh2(c[mt][nt][0] * dv, c[mt][nt][1] * dv);
            }
        }
        if (r1 < M) {
            float dv = g_dinv[r1];
#pragma unroll
            for (int nt = 0; nt < 4; nt++) {
                int col = bx * 128 + wn * 32 + nt * 8 + q2;
                g_hh[r1 * (F_HID/2) + (col >> 1)] = packh2(c[mt][nt][2] * dv, c[mt][nt][3] * dv);
            }
        }
    }
}

// ---------------- agg1 + bias + relu + GEMM2 fused (fp16 h gather) ----------------
// Block = 256 threads = 2 halves x 128. Each half processes alternate edges;
// lane f2 of a half owns feature pair (2*f2, 2*f2+1). fp32 accumulate.
__global__ __launch_bounds__(256) void k_agg1(const float* __restrict__ b1, int n) {
    __shared__ float w2s[F_OUT * F_HID];   // 40 KB
    __shared__ float hsm[F_HID];
    __shared__ float pA[128], pB[128];
    __shared__ int   jsm[256];
    int tid = threadIdx.x;
    for (int idx = tid; idx < F_OUT * F_HID; idx += 256) w2s[idx] = g_w2t[idx];
    __syncthreads();

    const int half = tid >> 7;        // 0 or 1
    const int f2   = tid & 127;       // half2 index
    const int lane = tid & 31, w = tid >> 5;
    const float bias0 = b1[2 * f2];
    const float bias1 = b1[2 * f2 + 1];

    for (int i = blockIdx.x; i < n; i += gridDim.x) {
        int start = g_rowptr[i];
        int end   = g_rowptr[i + 1];

        float acc0 = 0.f, acc1 = 0.f;
        if (half == 0) {   // self-loop term (already dinv-scaled), counted once
            unsigned u = g_hh[(long)i * 128 + f2];
            __half2 hh = *(__half2*)&u;
            acc0 = __low2float(hh);
            acc1 = __high2float(hh);
        }

        for (int base = start; base < end; base += 256) {
            int m = min(256, end - base);
            __syncthreads();
            if (tid < m) jsm[tid] = g_adj[base + tid];
            __syncthreads();
            for (int t = half; t < m; t += 2) {
                long j = jsm[t];
                unsigned u = g_hh[j * 128 + f2];
                __half2 hh = *(__half2*)&u;
                acc0 += __low2float(hh);
                acc1 += __high2float(hh);
            }
        }

        // combine halves
        if (half == 1) { pA[f2] = acc0; pB[f2] = acc1; }
        __syncthreads();
        if (half == 0) {
            float dv = g_dinv[i];
            float h0 = fmaxf(fmaf(acc0 + pA[f2], dv, bias0), 0.f);
            float h1 = fmaxf(fmaf(acc1 + pB[f2], dv, bias1), 0.f);
            hsm[2 * f2]     = h0;
            hsm[2 * f2 + 1] = h1;
        }
        __syncthreads();

        // GEMM2: 8 warps x 5 outputs; lane l owns f = l, l+32, ..., l+224
        float hv[8];
#pragma unroll
        for (int k = 0; k < 8; k++) hv[k] = hsm[(k << 5) + lane];
        float dvi = g_dinv[i];
#pragma unroll
        for (int oo = 0; oo < 5; oo++) {
            int o = w * 5 + oo;
            const float* wrow = &w2s[o * F_HID];
            float p = 0.f;
#pragma unroll
            for (int k = 0; k < 8; k++) p = fmaf(hv[k], wrow[(k << 5) + lane], p);
#pragma unroll
            for (int off = 16; off; off >>= 1)
                p += __shfl_xor_sync(0xffffffffu, p, off);
            if (lane == 0) g_h2[(long)i * F_OUT + o] = p * dvi;
        }
    }
}

// ---------------- agg2 + bias + log_softmax ----------------
__global__ __launch_bounds__(256) void k_agg2(const float* __restrict__ b2,
                                              float* __restrict__ outF,
                                              float* __restrict__ outL,
                                              int n, int writeL) {
    int lane = threadIdx.x & 31;
    int wid  = (blockIdx.x * blockDim.x + threadIdx.x) >> 5;
    int nw   = (gridDim.x * blockDim.x) >> 5;
    float bias0 = b2[lane];
    float bias1 = (lane < 8) ? b2[32 + lane] : 0.f;

    for (int i = wid; i < n; i += nw) {
        int start = g_rowptr[i];
        int end   = g_rowptr[i + 1];
        long ib = (long)i * F_OUT;
        float a0 = g_h2[ib + lane];
        float a1 = (lane < 8) ? g_h2[ib + 32 + lane] : 0.f;
        for (int e = start; e < end; e++) {
            int j = g_adj[e];
            long jb = (long)j * F_OUT;
            a0 += g_h2[jb + lane];
            if (lane < 8) a1 += g_h2[jb + 32 + lane];
        }
        float dv = g_dinv[i];
        float f0 = fmaf(a0, dv, bias0);
        float f1 = (lane < 8) ? fmaf(a1, dv, bias1) : -INFINITY;
        outF[ib + lane] = f0;
        if (lane < 8) outF[ib + 32 + lane] = f1;

        if (writeL) {
            float mx = fmaxf(f0, f1);
#pragma unroll
            for (int off = 16; off; off >>= 1)
                mx = fmaxf(mx, __shfl_xor_sync(0xffffffffu, mx, off));
            float s = expf(f0 - mx) + ((lane < 8) ? expf(f1 - mx) : 0.f);
#pragma unroll
            for (int off = 16; off; off >>= 1)
                s += __shfl_xor_sync(0xffffffffu, s, off);
            float lse = mx + logf(s);
            outL[ib + lane] = f0 - lse;
            if (lane < 8) outL[ib + 32 + lane] = f1 - lse;
        }
    }
}

// ---------------- launch ----------------
extern "C" void kernel_launch(void* const* d_in, const int* in_sizes, int n_in,
                              void* d_out, int out_size) {
    const float* x  = (const float*)d_in[0];
    const void*  ei = d_in[1];
    const float* W1 = (const float*)d_in[2];
    const float* b1 = (const float*)d_in[3];
    const float* W2 = (const float*)d_in[4];
    const float* b2 = (const float*)d_in[5];

    int n = in_sizes[0] / F_IN;
    int E = in_sizes[1] / 2;

    float* out = (float*)d_out;
    int half = n * F_OUT;
    float* outF = out;
    float* outL = out;
    int writeL = 0;
    if (out_size >= 2 * half) { outL = out + half; writeL = 1; }

    int nb = (n + 1023) >> 10;

    k_init   <<<(n + 255) / 256, 256>>>(n);
    k_detect <<<1024, 256>>>((const long long*)ei, E, n);
    k_convert<<<2048, 256>>>(ei, E, n);
    k_dinv   <<<(n + 255) / 256, 256>>>(n);
    k_scan1  <<<nb, 1024>>>(n);
    k_scan2  <<<1, 256>>>(nb);
    k_scan3  <<<(n + 255) / 256, 256>>>(n, E);
    k_fill   <<<2048, 256>>>(E);
    k_tw2    <<<(F_OUT * F_HID + 255) / 256, 256>>>(W2);
    k_tw1p   <<<((F_IN / 2) * F_HID + 255) / 256, 256>>>(W1);

    dim3 g1(2, (n + 127) / 128);
    k_gemm1_h<<<g1, 256>>>(x, n);

    k_agg1<<<4096, 256>>>(b1, n);
    k_agg2<<<2048, 256>>>(b2, outF, outL, n, writeL);
}